// round 3
// baseline (speedup 1.0000x reference)
#include <cuda_runtime.h>
#include <cstdint>

#define BB 128          // batch
#define PP 1200         // feature dim
#define NPB (BB * PP)   // 153600
#define MAXCH 8         // max p-chunks per iteration
#define MAXPC 240       // max p-chunk size

// Static scratch (no allocations allowed)
__device__ float g_h[NPB];               // h state (in-place updated)
__device__ float g_C[NPB];               // frozen-contribution cache C[b,q]
__device__ float g_partial[MAXCH * NPB]; // per-chunk partial sums [chunk][b][q]

__device__ __forceinline__ float f_p(float x) {
    float t = fminf(fmaxf(x, -1.0f), 1.0f);
    return t > 0.0f ? t : 0.01f * t;
}

// 16-byte streaming load as two packed f32x2 (64-bit) registers
struct U64x2 { unsigned long long a, b; };
__device__ __forceinline__ U64x2 ldg_cs_128(const void* p) {
    U64x2 r;
    asm("ld.global.cs.v2.u64 {%0,%1}, [%2];" : "=l"(r.a), "=l"(r.b) : "l"(p));
    return r;
}

// Packed dual-fp32 FMA: acc = m * hp + acc   (Blackwell f32x2 pipe)
#define FMA2(acc, m, hp) \
    asm("fma.rn.f32x2 %0, %1, %2, %0;" : "+l"(acc) : "l"(m), "l"(hp))

// ---------------------------------------------------------------------------
// init: h0 = f_p(query); C = 0
// ---------------------------------------------------------------------------
__global__ void init_kernel(const float* __restrict__ query) {
    int i = blockIdx.x * blockDim.x + threadIdx.x;
    if (i < NPB) {
        g_h[i] = f_p(query[i]);
        g_C[i] = 0.0f;
    }
}

// ---------------------------------------------------------------------------
// phase A: partial[ch][b][q] = sum_{p in chunk} h[b,p] * M[b,p,q]
// Grid: (nchunks, B, qtiles). Thread owns 4 consecutive q -> every warp
// LDG.128 is a contiguous 512B request (fully coalesced).
// pc = p-chunk size (240/120/60 depending on iteration).
// ---------------------------------------------------------------------------
__global__ void phaseA(const float* __restrict__ M, int n_on, int pc)
{
    const int ch  = blockIdx.x;
    const int b   = blockIdx.y;
    const int tid = threadIdx.x;
    const int pbase = ch * pc;

    __shared__ float2 hd[MAXPC];
    for (int i = tid; i < pc; i += blockDim.x) {
        float v = g_h[b * PP + pbase + i];
        hd[i] = make_float2(v, v);
    }
    __syncthreads();

    const int q0 = blockIdx.z * (blockDim.x * 4) + tid * 4;
    if (q0 >= n_on) return;

    const char* base = (const char*)(M + (size_t)b * PP * PP
                                       + (size_t)pbase * PP + q0);

    unsigned long long acc0 = 0, acc1 = 0;

    #pragma unroll 8
    for (int p = 0; p < pc; ++p) {
        unsigned long long hp = *reinterpret_cast<const unsigned long long*>(&hd[p]);
        U64x2 m = ldg_cs_128(base + (size_t)p * (PP * 4));
        FMA2(acc0, m.a, hp);
        FMA2(acc1, m.b, hp);
    }

    unsigned long long* out = reinterpret_cast<unsigned long long*>(
        g_partial + ((size_t)ch * BB + b) * PP + q0);
    out[0] = acc0;
    out[1] = acc1;
}

// ---------------------------------------------------------------------------
// phase B: mv = C + sum(partials); update h in place (q < n_on);
// fold newly-frozen chunk contributions into C. Last iter writes d_out
// (including frozen passthrough).
// ---------------------------------------------------------------------------
__global__ void phaseB(float* __restrict__ out,
                       int n_on, int nactive, int nchunks, int is_last)
{
    int i = blockIdx.x * blockDim.x + threadIdx.x;
    if (i >= NPB) return;
    int q = i % PP;
    int b = i / PP;

    float h = g_h[i];
    if (q >= n_on) {                    // frozen: state persists in place
        if (is_last) out[i] = h;
        return;
    }

    float sa = 0.0f, sf = 0.0f;
    const float* pp = g_partial + (size_t)b * PP + q;
    #pragma unroll
    for (int s = 0; s < MAXCH; ++s) {
        if (s >= nchunks) break;
        float v = pp[(size_t)s * NPB];
        if (s < nactive) sa += v; else sf += v;
    }

    float c  = g_C[i];
    float mv = sa + sf + c;
    if (nchunks > nactive) g_C[i] = c + sf;   // fold newly-frozen contribution

    float val = f_p(h * (0.8f + mv));
    if (is_last) out[i] = val; else g_h[i] = val;
}

// ---------------------------------------------------------------------------
extern "C" void kernel_launch(void* const* d_in, const int* in_sizes, int n_in,
                              void* d_out, int out_size)
{
    const float* query = (const float*)d_in[0];
    const float* M     = (const float*)d_in[1];
    float*       out   = (float*)d_out;

    init_kernel<<<(NPB + 255) / 256, 256>>>(query);

    // Per-iteration config: {n_on, prev, pc, blockDim}
    // pc chosen so grid stays large enough to saturate HBM on late iters.
    const int non_a [5] = {1200, 960, 720, 480, 240};
    const int prev_a[5] = {1200, 1200, 960, 720, 480};
    const int pc_a  [5] = {240, 240, 240, 120, 60};
    const int bd_a  [5] = {128, 128, 128, 128, 64};

    for (int it = 0; it < 5; ++it) {
        int non  = non_a[it];
        int prev = prev_a[it];
        int pc   = pc_a[it];
        int bd   = bd_a[it];

        int nchunks = prev / pc;        // p range read this iter: [0, prev)
        int nact    = non / pc;         // active p range: [0, non)
        int qtiles  = (non + bd * 4 - 1) / (bd * 4);

        dim3 gA(nchunks, BB, qtiles);
        phaseA<<<gA, bd>>>(M, non, pc);
        phaseB<<<(NPB + 255) / 256, 256>>>(out, non, nact, nchunks,
                                           it == 4 ? 1 : 0);
    }
}

// round 4
// speedup vs baseline: 1.2032x; 1.2032x over previous
#include <cuda_runtime.h>
#include <cstdint>

#define BB 128          // batch
#define PP 1200         // feature dim
#define NPB (BB * PP)   // 153600
#define MAXCH 8         // max p-chunks per iteration
#define MAXPC 240       // max p-chunk size

// Static scratch (no allocations allowed)
__device__ float g_h[NPB];               // h state (in-place updated)
__device__ float g_C[NPB];               // frozen-contribution cache C[b,q]
__device__ float g_partial[MAXCH * NPB]; // per-chunk partial sums [chunk][b][q]

__device__ __forceinline__ float f_p(float x) {
    float t = fminf(fmaxf(x, -1.0f), 1.0f);
    return t > 0.0f ? t : 0.01f * t;
}

// 16-byte streaming load as two packed f32x2 (64-bit) registers
struct U64x2 { unsigned long long a, b; };
__device__ __forceinline__ U64x2 ldg_cs_128(const void* p) {
    U64x2 r;
    asm("ld.global.cs.v2.u64 {%0,%1}, [%2];" : "=l"(r.a), "=l"(r.b) : "l"(p));
    return r;
}

// Packed dual-fp32 FMA: acc = m * hp + acc   (Blackwell f32x2 pipe)
#define FMA2(acc, m, hp) \
    asm("fma.rn.f32x2 %0, %1, %2, %0;" : "+l"(acc) : "l"(m), "l"(hp))

// ---------------------------------------------------------------------------
// init: h0 = f_p(query); C = 0
// ---------------------------------------------------------------------------
__global__ void init_kernel(const float* __restrict__ query) {
    int i = blockIdx.x * blockDim.x + threadIdx.x;
    if (i < NPB) {
        g_h[i] = f_p(query[i]);
        g_C[i] = 0.0f;
    }
}

// ---------------------------------------------------------------------------
// phase A: partial[ch][b][q] = sum_{p in chunk} h[b,p] * M[b,p,q]
// Grid: (nchunks, B, qtiles). Thread owns 4 consecutive q -> every warp
// LDG.128 is a contiguous request (fully coalesced).
// PC is a compile-time p-chunk size so the mainloop trip count is static
// (ptxas front-batches the loads; runtime bound cost ~3% in R3).
// ---------------------------------------------------------------------------
template<int PC>
__global__ void phaseA(const float* __restrict__ M, int n_on)
{
    const int ch  = blockIdx.x;
    const int b   = blockIdx.y;
    const int tid = threadIdx.x;
    const int pbase = ch * PC;

    __shared__ float2 hd[PC];
    #pragma unroll
    for (int i = tid; i < PC; i += blockDim.x) {
        float v = g_h[b * PP + pbase + i];
        hd[i] = make_float2(v, v);
    }
    __syncthreads();

    const int q0 = blockIdx.z * (blockDim.x * 4) + tid * 4;
    if (q0 >= n_on) return;

    const char* base = (const char*)(M + (size_t)b * PP * PP
                                       + (size_t)pbase * PP + q0);

    unsigned long long acc0 = 0, acc1 = 0;

    #pragma unroll 8
    for (int p = 0; p < PC; ++p) {
        unsigned long long hp = *reinterpret_cast<const unsigned long long*>(&hd[p]);
        U64x2 m = ldg_cs_128(base + (size_t)p * (PP * 4));
        FMA2(acc0, m.a, hp);
        FMA2(acc1, m.b, hp);
    }

    unsigned long long* out = reinterpret_cast<unsigned long long*>(
        g_partial + ((size_t)ch * BB + b) * PP + q0);
    out[0] = acc0;
    out[1] = acc1;
}

// ---------------------------------------------------------------------------
// phase B: mv = C + sum(partials); update h in place (q < n_on);
// fold newly-frozen chunk contributions into C. Last iter writes d_out
// (including frozen passthrough).
// ---------------------------------------------------------------------------
__global__ void phaseB(float* __restrict__ out,
                       int n_on, int nactive, int nchunks, int is_last)
{
    int i = blockIdx.x * blockDim.x + threadIdx.x;
    if (i >= NPB) return;
    int q = i % PP;
    int b = i / PP;

    float h = g_h[i];
    if (q >= n_on) {                    // frozen: state persists in place
        if (is_last) out[i] = h;
        return;
    }

    float sa = 0.0f, sf = 0.0f;
    const float* pp = g_partial + (size_t)b * PP + q;
    #pragma unroll
    for (int s = 0; s < MAXCH; ++s) {
        if (s >= nchunks) break;
        float v = pp[(size_t)s * NPB];
        if (s < nactive) sa += v; else sf += v;
    }

    float c  = g_C[i];
    float mv = sa + sf + c;
    if (nchunks > nactive) g_C[i] = c + sf;   // fold newly-frozen contribution

    float val = f_p(h * (0.8f + mv));
    if (is_last) out[i] = val; else g_h[i] = val;
}

// ---------------------------------------------------------------------------
extern "C" void kernel_launch(void* const* d_in, const int* in_sizes, int n_in,
                              void* d_out, int out_size)
{
    const float* query = (const float*)d_in[0];
    const float* M     = (const float*)d_in[1];
    float*       out   = (float*)d_out;

    init_kernel<<<(NPB + 255) / 256, 256>>>(query);

    // Per-iteration config. pc compile-time via template dispatch; pc chosen
    // so the grid stays large enough to saturate HBM on late iterations.
    const int non_a [5] = {1200, 960, 720, 480, 240};
    const int prev_a[5] = {1200, 1200, 960, 720, 480};
    const int pc_a  [5] = {240, 240, 240, 120, 60};
    const int bd_a  [5] = {128, 128, 128, 128, 64};

    for (int it = 0; it < 5; ++it) {
        int non  = non_a[it];
        int prev = prev_a[it];
        int pc   = pc_a[it];
        int bd   = bd_a[it];

        int nchunks = prev / pc;        // p range read this iter: [0, prev)
        int nact    = non / pc;         // active p range: [0, non)
        int qtiles  = (non + bd * 4 - 1) / (bd * 4);

        dim3 gA(nchunks, BB, qtiles);
        if (pc == 240)      phaseA<240><<<gA, bd>>>(M, non);
        else if (pc == 120) phaseA<120><<<gA, bd>>>(M, non);
        else                phaseA<60><<<gA, bd>>>(M, non);

        phaseB<<<(NPB + 255) / 256, 256>>>(out, non, nact, nchunks,
                                           it == 4 ? 1 : 0);
    }
}